// round 1
// baseline (speedup 1.0000x reference)
#include <cuda_runtime.h>
#include <math.h>

#define NW 16
#define NTHREADS 512

// ---------------- device globals (no allocation allowed) ----------------
__device__ double g_part[256];
__device__ float  g_cst;
__device__ float  g_G0[2048];   // (Wl0 @ Wf0) / (8*sqrt(32)), [64][32]
__device__ float  g_G1[2048];   // (Wl1 @ Wf1) / (8*sqrt(32))

// ---------------- K1: partial sums of the silu-normalization integral ----
__global__ void k_integral() {
    __shared__ double red[256];
    const double dz = 24.0 / 200000.0;
    double local = 0.0;
    for (int j = blockIdx.x * blockDim.x + threadIdx.x; j <= 200000;
         j += gridDim.x * blockDim.x) {
        double z   = -12.0 + dz * (double)j;
        double s   = z / (1.0 + exp(-z));
        double phi = exp(-0.5 * z * z) * 0.3989422804014326779399461;
        double y   = s * s * phi;
        if (j == 0 || j == 200000) y *= 0.5;   // trapezoid endpoints
        local += y;
    }
    red[threadIdx.x] = local;
    __syncthreads();
    for (int o = 128; o > 0; o >>= 1) {
        if (threadIdx.x < o) red[threadIdx.x] += red[threadIdx.x + o];
        __syncthreads();
    }
    if (threadIdx.x == 0) g_part[blockIdx.x] = red[0];
}

// ---------------- K2: finalize SILU_CST; precompute G0/G1 ----------------
__global__ void k_precompute(const float* __restrict__ Wl0, const float* __restrict__ Wf0,
                             const float* __restrict__ Wl1, const float* __restrict__ Wf1) {
    __shared__ double red[256];
    int t = threadIdx.x;
    red[t] = (t < 200) ? g_part[t] : 0.0;
    __syncthreads();
    for (int o = 128; o > 0; o >>= 1) {
        if (t < o) red[t] += red[t + o];
        __syncthreads();
    }
    if (t == 0) {
        double I = red[0] * (24.0 / 200000.0);
        g_cst = (float)(1.0 / sqrt(I));
    }
    const float scale = 0.125f * 0.17677669529663687f;  // 1/8 * 1/sqrt(32)
    for (int idx = t; idx < 64 * 32; idx += blockDim.x) {
        int u = idx >> 5, w = idx & 31;
        float a0 = 0.f, a1 = 0.f;
        #pragma unroll
        for (int m = 0; m < 32; m++) {
            a0 = fmaf(Wl0[u * 32 + m], Wf0[m * 32 + w], a0);
            a1 = fmaf(Wl1[u * 32 + m], Wf1[m * 32 + w], a1);
        }
        g_G0[idx] = a0 * scale;
        g_G1[idx] = a1 * scale;
    }
}

// ---------------- main kernel ----------------
__device__ __forceinline__ float silu_n(float x, float c) {
    return c * __fdividef(x, 1.0f + __expf(-x));
}

__global__ __launch_bounds__(NTHREADS, 1)
void k_main(const float* __restrict__ x1a, const float* __restrict__ x1b,
            const float* __restrict__ x2,  const float* __restrict__ scalars,
            const float* __restrict__ w0,  const float* __restrict__ w1,
            const float* __restrict__ w2,  const float* __restrict__ w3,
            const float* __restrict__ Wm1, const float* __restrict__ Wm2,
            const float* __restrict__ Wm3,
            float* __restrict__ out, int E)
{
    extern __shared__ float smem[];
    float2* sWm1 = (float2*)smem;                  // [64][32] pairs (col l, l+32)
    float2* sWm2 = (float2*)(smem + 4096);
    float4* sWm3 = (float4*)(smem + 8192);         // [64][32] quads (cols l,l+32,l+64,l+96)
    float4* sW4  = (float4*)(smem + 16384);        // {w0,w1,w2,w3}[u][l]
    float2* sG   = (float2*)(smem + 24576);        // {G0,G1}[u][l]
    float*  scratch = smem + 28672;                // NW * 1024 floats

    const int tid = threadIdx.x;
    for (int idx = tid; idx < 2048; idx += NTHREADS) {
        int i = idx >> 5, l = idx & 31;
        sWm1[idx] = make_float2(Wm1[i * 64 + l], Wm1[i * 64 + l + 32]);
        sWm2[idx] = make_float2(Wm2[i * 64 + l], Wm2[i * 64 + l + 32]);
        sWm3[idx] = make_float4(Wm3[i * 128 + l],      Wm3[i * 128 + l + 32],
                                Wm3[i * 128 + l + 64], Wm3[i * 128 + l + 96]);
        sW4[idx]  = make_float4(w0[idx], w1[idx], w2[idx], w3[idx]);
        sG[idx]   = make_float2(g_G0[idx], g_G1[idx]);
    }
    __syncthreads();
    const float cst = g_cst;

    const int wid = tid >> 5;
    const int l   = tid & 31;
    float* sv  = scratch + wid * 1024;   // [2][64]  MLP vector
    float* sc  = sv  + 128;              // [2][64]  s0
    float* ss1 = sc  + 128;              // [2][3][64]  s1 per-k
    float* sm0 = ss1 + 384;              // [2][64]
    float* smm = sm0 + 128;              // [2][32]
    float* smr = smm + 64;               // [2][3][32]

    const int warp_gid = blockIdx.x * NW + wid;
    const int stride   = gridDim.x * NW * 2;
    const float PW  = 0.125f;
    const float PWI = 0.125f * 0.57735026918962576f;  // PW / sqrt(3)

    for (int e0 = warp_gid * 2; e0 < E; e0 += stride) {
        const int e1 = (e0 + 1 < E) ? (e0 + 1) : e0;
        __syncwarp();

        // ---- MLP input
        const float* scA = scalars + (size_t)e0 * 64;
        const float* scB = scalars + (size_t)e1 * 64;
        sv[l]      = scA[l];      sv[32 + l] = scA[32 + l];
        sv[64 + l] = scB[l];      sv[96 + l] = scB[32 + l];
        __syncwarp();

        // ---- stage 1: h1 = cst * silu(v @ Wm1 / 8)
        float aA0 = 0.f, aA1 = 0.f, aB0 = 0.f, aB1 = 0.f;
        #pragma unroll 4
        for (int i = 0; i < 64; i += 4) {
            float4 vA = *(const float4*)(sv + i);
            float4 vB = *(const float4*)(sv + 64 + i);
            const float* pA = (const float*)&vA;
            const float* pB = (const float*)&vB;
            #pragma unroll
            for (int j = 0; j < 4; j++) {
                float2 w = sWm1[(i + j) * 32 + l];
                aA0 = fmaf(pA[j], w.x, aA0); aA1 = fmaf(pA[j], w.y, aA1);
                aB0 = fmaf(pB[j], w.x, aB0); aB1 = fmaf(pB[j], w.y, aB1);
            }
        }
        __syncwarp();
        sv[l]      = silu_n(aA0 * 0.125f, cst);
        sv[32 + l] = silu_n(aA1 * 0.125f, cst);
        sv[64 + l] = silu_n(aB0 * 0.125f, cst);
        sv[96 + l] = silu_n(aB1 * 0.125f, cst);
        __syncwarp();

        // ---- stage 2: h2 = cst * silu(h1 @ Wm2 / 8)
        aA0 = aA1 = aB0 = aB1 = 0.f;
        #pragma unroll 4
        for (int i = 0; i < 64; i += 4) {
            float4 vA = *(const float4*)(sv + i);
            float4 vB = *(const float4*)(sv + 64 + i);
            const float* pA = (const float*)&vA;
            const float* pB = (const float*)&vB;
            #pragma unroll
            for (int j = 0; j < 4; j++) {
                float2 w = sWm2[(i + j) * 32 + l];
                aA0 = fmaf(pA[j], w.x, aA0); aA1 = fmaf(pA[j], w.y, aA1);
                aB0 = fmaf(pB[j], w.x, aB0); aB1 = fmaf(pB[j], w.y, aB1);
            }
        }
        __syncwarp();
        sv[l]      = silu_n(aA0 * 0.125f, cst);
        sv[32 + l] = silu_n(aA1 * 0.125f, cst);
        sv[64 + l] = silu_n(aB0 * 0.125f, cst);
        sv[96 + l] = silu_n(aB1 * 0.125f, cst);
        __syncwarp();

        // ---- stage 3: weights = h2 @ Wm3 / 8   (lane l owns cols l, l+32, l+64, l+96)
        float wA0 = 0.f, wA1 = 0.f, wA2 = 0.f, wA3 = 0.f;
        float wB0 = 0.f, wB1 = 0.f, wB2 = 0.f, wB3 = 0.f;
        #pragma unroll 4
        for (int i = 0; i < 64; i += 4) {
            float4 vA = *(const float4*)(sv + i);
            float4 vB = *(const float4*)(sv + 64 + i);
            const float* pA = (const float*)&vA;
            const float* pB = (const float*)&vB;
            #pragma unroll
            for (int j = 0; j < 4; j++) {
                float4 w = sWm3[(i + j) * 32 + l];
                wA0 = fmaf(pA[j], w.x, wA0); wA1 = fmaf(pA[j], w.y, wA1);
                wA2 = fmaf(pA[j], w.z, wA2); wA3 = fmaf(pA[j], w.w, wA3);
                wB0 = fmaf(pB[j], w.x, wB0); wB1 = fmaf(pB[j], w.y, wB1);
                wB2 = fmaf(pB[j], w.z, wB2); wB3 = fmaf(pB[j], w.w, wB3);
            }
        }
        wA0 *= 0.125f; wA1 *= 0.125f; wA2 *= 0.125f; wA3 *= 0.125f;
        wB0 *= 0.125f; wB1 *= 0.125f; wB2 *= 0.125f; wB3 *= 0.125f;

        // ---- TP staging: s0 and s1 (per-k) into broadcast buffers
        float4 yA = *(const float4*)(x2 + (size_t)e0 * 4);  // y0, y1x, y1y, y1z
        float4 yB = *(const float4*)(x2 + (size_t)e1 * 4);
        const float* raA = x1a + (size_t)e0 * 128;
        const float* rbA = x1b + (size_t)e0 * 128;
        const float* raB = x1a + (size_t)e1 * 128;
        const float* rbB = x1b + (size_t)e1 * 128;

        sc[l]       = raA[l];           sc[32 + l]  = rbA[l];
        sc[64 + l]  = raB[l];           sc[96 + l]  = rbB[l];
        ss1[l]        = raA[32 + 3 * l];  ss1[32 + l]  = rbA[32 + 3 * l];
        ss1[64 + l]   = raA[33 + 3 * l];  ss1[96 + l]  = rbA[33 + 3 * l];
        ss1[128 + l]  = raA[34 + 3 * l];  ss1[160 + l] = rbA[34 + 3 * l];
        ss1[192 + l]  = raB[32 + 3 * l];  ss1[224 + l] = rbB[32 + 3 * l];
        ss1[256 + l]  = raB[33 + 3 * l];  ss1[288 + l] = rbB[33 + 3 * l];
        ss1[320 + l]  = raB[34 + 3 * l];  ss1[352 + l] = rbB[34 + 3 * l];
        __syncwarp();

        // ---- TP contractions (y0/y1 hoisted out)
        float t0A = 0.f, qA = 0.f, u0A = 0.f, u1A = 0.f, u2A = 0.f, r0A = 0.f, r1A = 0.f, r2A = 0.f;
        float t0B = 0.f, qB = 0.f, u0B = 0.f, u1B = 0.f, u2B = 0.f, r0B = 0.f, r1B = 0.f, r2B = 0.f;
        #pragma unroll 4
        for (int i = 0; i < 64; i += 4) {
            float4 cA  = *(const float4*)(sc + i);
            float4 cB  = *(const float4*)(sc + 64 + i);
            float4 sA0 = *(const float4*)(ss1 + i);
            float4 sA1 = *(const float4*)(ss1 + 64 + i);
            float4 sA2 = *(const float4*)(ss1 + 128 + i);
            float4 sB0 = *(const float4*)(ss1 + 192 + i);
            float4 sB1 = *(const float4*)(ss1 + 256 + i);
            float4 sB2 = *(const float4*)(ss1 + 320 + i);
            const float* pcA  = (const float*)&cA;
            const float* pcB  = (const float*)&cB;
            const float* pA0  = (const float*)&sA0;
            const float* pA1  = (const float*)&sA1;
            const float* pA2  = (const float*)&sA2;
            const float* pB0  = (const float*)&sB0;
            const float* pB1  = (const float*)&sB1;
            const float* pB2  = (const float*)&sB2;
            #pragma unroll
            for (int j = 0; j < 4; j++) {
                float4 w = sW4[(i + j) * 32 + l];
                t0A = fmaf(pcA[j], w.x, t0A);  qA  = fmaf(pcA[j], w.z, qA);
                u0A = fmaf(pA0[j], w.y, u0A);  r0A = fmaf(pA0[j], w.w, r0A);
                u1A = fmaf(pA1[j], w.y, u1A);  r1A = fmaf(pA1[j], w.w, r1A);
                u2A = fmaf(pA2[j], w.y, u2A);  r2A = fmaf(pA2[j], w.w, r2A);
                t0B = fmaf(pcB[j], w.x, t0B);  qB  = fmaf(pcB[j], w.z, qB);
                u0B = fmaf(pB0[j], w.y, u0B);  r0B = fmaf(pB0[j], w.w, r0B);
                u1B = fmaf(pB1[j], w.y, u1B);  r1B = fmaf(pB1[j], w.w, r1B);
                u2B = fmaf(pB2[j], w.y, u2B);  r2B = fmaf(pB2[j], w.w, r2B);
            }
        }
        __syncwarp();

        // ---- apply per-path scales + event weights, stage m-vectors
        {
            float p0 = PW * yA.x * t0A;
            float p1 = PWI * (fmaf(yA.y, u0A, fmaf(yA.z, u1A, yA.w * u2A)));
            sm0[l]      = p0 * wA0;
            sm0[32 + l] = p1 * wA1;
            smm[l]      = PW * qA * wA2;
            float m3s = PW * wA3;
            smr[l]      = r0A * m3s;
            smr[32 + l] = r1A * m3s;
            smr[64 + l] = r2A * m3s;
        }
        {
            float p0 = PW * yB.x * t0B;
            float p1 = PWI * (fmaf(yB.y, u0B, fmaf(yB.z, u1B, yB.w * u2B)));
            sm0[64 + l] = p0 * wB0;
            sm0[96 + l] = p1 * wB1;
            smm[32 + l] = PW * qB * wB2;
            float m3s = PW * wB3;
            smr[96 + l]  = r0B * m3s;
            smr[128 + l] = r1B * m3s;
            smr[160 + l] = r2B * m3s;
        }
        __syncwarp();

        // ---- epilogue: fused (Wl @ Wf) projection
        float o0A = 0.f, tlA = 0.f, t0kA = 0.f, t1kA = 0.f, t2kA = 0.f;
        float o0B = 0.f, tlB = 0.f, t0kB = 0.f, t1kB = 0.f, t2kB = 0.f;
        #pragma unroll
        for (int i = 0; i < 32; i += 4) {
            float4 mA = *(const float4*)(sm0 + i);
            float4 nA = *(const float4*)(smm + i);
            float4 mB = *(const float4*)(sm0 + 64 + i);
            float4 nB = *(const float4*)(smm + 32 + i);
            const float* pmA = (const float*)&mA;
            const float* pnA = (const float*)&nA;
            const float* pmB = (const float*)&mB;
            const float* pnB = (const float*)&nB;
            #pragma unroll
            for (int j = 0; j < 4; j++) {
                float2 g = sG[(i + j) * 32 + l];
                o0A = fmaf(pmA[j], g.x, o0A);  tlA = fmaf(pnA[j], g.y, tlA);
                o0B = fmaf(pmB[j], g.x, o0B);  tlB = fmaf(pnB[j], g.y, tlB);
            }
        }
        #pragma unroll
        for (int i = 0; i < 32; i += 4) {
            float4 mA  = *(const float4*)(sm0 + 32 + i);
            float4 rA0 = *(const float4*)(smr + i);
            float4 rA1 = *(const float4*)(smr + 32 + i);
            float4 rA2 = *(const float4*)(smr + 64 + i);
            float4 mB  = *(const float4*)(sm0 + 96 + i);
            float4 rB0 = *(const float4*)(smr + 96 + i);
            float4 rB1 = *(const float4*)(smr + 128 + i);
            float4 rB2 = *(const float4*)(smr + 160 + i);
            const float* pmA = (const float*)&mA;
            const float* pa0 = (const float*)&rA0;
            const float* pa1 = (const float*)&rA1;
            const float* pa2 = (const float*)&rA2;
            const float* pmB = (const float*)&mB;
            const float* pb0 = (const float*)&rB0;
            const float* pb1 = (const float*)&rB1;
            const float* pb2 = (const float*)&rB2;
            #pragma unroll
            for (int j = 0; j < 4; j++) {
                float2 g = sG[(32 + i + j) * 32 + l];
                o0A  = fmaf(pmA[j], g.x, o0A);
                t0kA = fmaf(pa0[j], g.y, t0kA);
                t1kA = fmaf(pa1[j], g.y, t1kA);
                t2kA = fmaf(pa2[j], g.y, t2kA);
                o0B  = fmaf(pmB[j], g.x, o0B);
                t0kB = fmaf(pb0[j], g.y, t0kB);
                t1kB = fmaf(pb1[j], g.y, t1kB);
                t2kB = fmaf(pb2[j], g.y, t2kB);
            }
        }

        // ---- write output: [o0 (32) | o1 (32x3 row-major)]
        float* oA = out + (size_t)e0 * 128;
        float* oB = out + (size_t)e1 * 128;
        oA[l]          = o0A;
        oA[32 + 3 * l] = fmaf(yA.y, tlA, yA.x * t0kA);
        oA[33 + 3 * l] = fmaf(yA.z, tlA, yA.x * t1kA);
        oA[34 + 3 * l] = fmaf(yA.w, tlA, yA.x * t2kA);
        oB[l]          = o0B;
        oB[32 + 3 * l] = fmaf(yB.y, tlB, yB.x * t0kB);
        oB[33 + 3 * l] = fmaf(yB.z, tlB, yB.x * t1kB);
        oB[34 + 3 * l] = fmaf(yB.w, tlB, yB.x * t2kB);
    }
}

// ---------------- launch ----------------
extern "C" void kernel_launch(void* const* d_in, const int* in_sizes, int n_in,
                              void* d_out, int out_size) {
    const float* x1a     = (const float*)d_in[0];
    const float* x1b     = (const float*)d_in[1];
    const float* x2      = (const float*)d_in[2];
    const float* scalars = (const float*)d_in[3];
    const float* w0      = (const float*)d_in[4];
    const float* w1      = (const float*)d_in[5];
    const float* w2      = (const float*)d_in[6];
    const float* w3      = (const float*)d_in[7];
    const float* Wl0     = (const float*)d_in[8];
    const float* Wl1     = (const float*)d_in[9];
    const float* Wm1     = (const float*)d_in[10];
    const float* Wm2     = (const float*)d_in[11];
    const float* Wm3     = (const float*)d_in[12];
    const float* Wf0     = (const float*)d_in[13];
    const float* Wf1     = (const float*)d_in[14];
    const int E = in_sizes[0] / 128;

    k_integral<<<200, 256>>>();
    k_precompute<<<1, 256>>>(Wl0, Wf0, Wl1, Wf1);

    int sms = 148;
    cudaDeviceGetAttribute(&sms, cudaDevAttrMultiProcessorCount, 0);
    size_t smem = (size_t)(28672 + NW * 1024) * sizeof(float);
    cudaFuncSetAttribute(k_main, cudaFuncAttributeMaxDynamicSharedMemorySize, (int)smem);
    k_main<<<sms, NTHREADS, smem>>>(x1a, x1b, x2, scalars, w0, w1, w2, w3,
                                    Wm1, Wm2, Wm3, (float*)d_out, E);
}

// round 4
// speedup vs baseline: 1.4228x; 1.4228x over previous
#include <cuda_runtime.h>
#include <math.h>

#define NW 16
#define NTHREADS 512

typedef unsigned long long ull;

// ---------------- device globals (no allocation allowed) ----------------
__device__ double g_part[256];
__device__ float  g_cst;
__device__ float  g_G0[2048];   // (Wl0 @ Wf0) / (8*sqrt(32)), [64][32]
__device__ float  g_G1[2048];   // (Wl1 @ Wf1) / (8*sqrt(32))

// ---------------- packed fp32x2 helpers (sm_103a FFMA2 path) ----------------
__device__ __forceinline__ ull pk(float a, float b) {
    ull r; asm("mov.b64 %0, {%1, %2};" : "=l"(r) : "f"(a), "f"(b)); return r;
}
__device__ __forceinline__ ull sp(float a) { return pk(a, a); }
__device__ __forceinline__ void upk(ull v, float& a, float& b) {
    asm("mov.b64 {%0, %1}, %2;" : "=f"(a), "=f"(b) : "l"(v));
}
__device__ __forceinline__ void fma2(ull& d, ull a, ull b) {
    asm("fma.rn.f32x2 %0, %1, %2, %0;" : "+l"(d) : "l"(a), "l"(b));
}
__device__ __forceinline__ ull mul2(ull a, ull b) {
    ull d; asm("mul.rn.f32x2 %0, %1, %2;" : "=l"(d) : "l"(a), "l"(b)); return d;
}
__device__ __forceinline__ ull ldp(const float2* p) {
    return *reinterpret_cast<const ull*>(p);
}
__device__ __forceinline__ void stp(float2* p, ull v) {
    *reinterpret_cast<ull*>(p) = v;
}

// ---------------- K1: silu-normalization integral (fp32 fast path) ----------
__global__ void k_integral() {
    __shared__ double red[256];
    const double dz = 24.0 / 200000.0;
    float local = 0.f;
    double acc = 0.0;
    for (int j = blockIdx.x * blockDim.x + threadIdx.x; j <= 200000;
         j += gridDim.x * blockDim.x) {
        double zd = -12.0 + dz * (double)j;
        float z   = (float)zd;
        float s   = z * (1.0f / (1.0f + __expf(-z)));
        float phi = __expf(-0.5f * z * z) * 0.39894228040143268f;
        float y   = s * s * phi;
        if (j == 0 || j == 200000) y *= 0.5f;
        local += y;
        acc   += 0.0;  // keep acc referenced
    }
    red[threadIdx.x] = (double)local;
    __syncthreads();
    for (int o = 128; o > 0; o >>= 1) {
        if (threadIdx.x < o) red[threadIdx.x] += red[threadIdx.x + o];
        __syncthreads();
    }
    if (threadIdx.x == 0) g_part[blockIdx.x] = red[0];
}

// ---------------- K2: finalize SILU_CST; precompute G0/G1 ----------------
__global__ void k_precompute(const float* __restrict__ Wl0, const float* __restrict__ Wf0,
                             const float* __restrict__ Wl1, const float* __restrict__ Wf1) {
    __shared__ double red[256];
    int t = threadIdx.x;
    red[t] = (t < 200) ? g_part[t] : 0.0;
    __syncthreads();
    for (int o = 128; o > 0; o >>= 1) {
        if (t < o) red[t] += red[t + o];
        __syncthreads();
    }
    if (t == 0) {
        double I = red[0] * (24.0 / 200000.0);
        g_cst = (float)(1.0 / sqrt(I));
    }
    const float scale = 0.125f * 0.17677669529663687f;  // 1/8 * 1/sqrt(32)
    for (int idx = t; idx < 64 * 32; idx += blockDim.x) {
        int u = idx >> 5, w = idx & 31;
        float a0 = 0.f, a1 = 0.f;
        #pragma unroll
        for (int m = 0; m < 32; m++) {
            a0 = fmaf(Wl0[u * 32 + m], Wf0[m * 32 + w], a0);
            a1 = fmaf(Wl1[u * 32 + m], Wf1[m * 32 + w], a1);
        }
        g_G0[idx] = a0 * scale;
        g_G1[idx] = a1 * scale;
    }
}

// ---------------- main kernel ----------------
__device__ __forceinline__ float silu_n(float x, float c) {
    return c * __fdividef(x, 1.0f + __expf(-x));
}

// per-warp scratch: 640 float2 (sv 128 | sc 128 | ss1 384; sm0/smm/smr alias ss1)
#define WARP_F2 640

__global__ __launch_bounds__(NTHREADS, 1)
void k_main(const float* __restrict__ x1a, const float* __restrict__ x1b,
            const float* __restrict__ x2,  const float* __restrict__ scalars,
            const float* __restrict__ w0,  const float* __restrict__ w1,
            const float* __restrict__ w2,  const float* __restrict__ w3,
            const float* __restrict__ Wm1, const float* __restrict__ Wm2,
            const float* __restrict__ Wm3,
            float* __restrict__ out, int E)
{
    extern __shared__ float smem[];
    float2* sWm1 = (float2*)smem;                  // [64][32] (col l, l+32)
    float2* sWm2 = (float2*)(smem + 4096);
    float4* sWm3 = (float4*)(smem + 8192);         // [64][32] (cols l,l+32,l+64,l+96)
    float4* sW4  = (float4*)(smem + 16384);        // {w0,w1,w2,w3}[u][l]
    float2* sG   = (float2*)(smem + 24576);        // {G0,G1}[u][l]
    float2* scr  = (float2*)(smem + 28672);        // NW * WARP_F2 float2

    const int tid = threadIdx.x;
    for (int idx = tid; idx < 2048; idx += NTHREADS) {
        int i = idx >> 5, l = idx & 31;
        sWm1[idx] = make_float2(Wm1[i * 64 + l], Wm1[i * 64 + l + 32]);
        sWm2[idx] = make_float2(Wm2[i * 64 + l], Wm2[i * 64 + l + 32]);
        sWm3[idx] = make_float4(Wm3[i * 128 + l],      Wm3[i * 128 + l + 32],
                                Wm3[i * 128 + l + 64], Wm3[i * 128 + l + 96]);
        sW4[idx]  = make_float4(w0[idx], w1[idx], w2[idx], w3[idx]);
        sG[idx]   = make_float2(g_G0[idx], g_G1[idx]);
    }
    __syncthreads();
    const float cst = g_cst;

    const int wid = tid >> 5;
    const int l   = tid & 31;
    float2* sv2  = scr + wid * WARP_F2;   // [pair][64]
    float2* sc2  = sv2 + 128;             // [pair][64]
    float2* ss12 = sv2 + 256;             // [k][pair][64]
    float2* sm02 = sv2 + 256;             // alias: [pair][64]
    float2* smm2 = sv2 + 384;             // alias: [pair][32]
    float2* smr2 = sv2 + 448;             // alias: [k][pair][32]

    const int warp_gid = blockIdx.x * NW + wid;
    const int wstride  = gridDim.x * NW;
    const float PW  = 0.125f;
    const float PWI = 0.125f * 0.57735026918962576f;  // PW / sqrt(3)
    const ull c8   = sp(0.125f);
    const ull cPW8 = sp(0.125f * PW);

    const int niter = (E + 3) >> 2;
    for (int it = warp_gid; it < niter; it += wstride) {
        const int e0 = it * 4;
        const int e1 = (e0 + 1 < E) ? e0 + 1 : E - 1;
        const int e2 = (e0 + 2 < E) ? e0 + 2 : E - 1;
        const int e3 = (e0 + 3 < E) ? e0 + 3 : E - 1;
        __syncwarp();

        // ---- stage scalars (pair-interleaved)
        {
            const float* sA = scalars + (size_t)e0 * 64;
            const float* sB = scalars + (size_t)e1 * 64;
            const float* sC = scalars + (size_t)e2 * 64;
            const float* sD = scalars + (size_t)e3 * 64;
            sv2[l]      = make_float2(sA[l],      sB[l]);
            sv2[32 + l] = make_float2(sA[32 + l], sB[32 + l]);
            sv2[64 + l] = make_float2(sC[l],      sD[l]);
            sv2[96 + l] = make_float2(sC[32 + l], sD[32 + l]);
        }
        __syncwarp();

        // ---- MLP stage 1
        {
            ull a0P = 0, a1P = 0, a0Q = 0, a1Q = 0;
            #pragma unroll 8
            for (int i = 0; i < 64; i++) {
                ull vP = ldp(sv2 + i), vQ = ldp(sv2 + 64 + i);
                float2 w = sWm1[i * 32 + l];
                ull wx = sp(w.x), wy = sp(w.y);
                fma2(a0P, vP, wx); fma2(a1P, vP, wy);
                fma2(a0Q, vQ, wx); fma2(a1Q, vQ, wy);
            }
            __syncwarp();
            float xa, xb;
            upk(a0P, xa, xb); sv2[l]      = make_float2(silu_n(xa*0.125f,cst), silu_n(xb*0.125f,cst));
            upk(a1P, xa, xb); sv2[32 + l] = make_float2(silu_n(xa*0.125f,cst), silu_n(xb*0.125f,cst));
            upk(a0Q, xa, xb); sv2[64 + l] = make_float2(silu_n(xa*0.125f,cst), silu_n(xb*0.125f,cst));
            upk(a1Q, xa, xb); sv2[96 + l] = make_float2(silu_n(xa*0.125f,cst), silu_n(xb*0.125f,cst));
            __syncwarp();
        }

        // ---- MLP stage 2
        {
            ull a0P = 0, a1P = 0, a0Q = 0, a1Q = 0;
            #pragma unroll 8
            for (int i = 0; i < 64; i++) {
                ull vP = ldp(sv2 + i), vQ = ldp(sv2 + 64 + i);
                float2 w = sWm2[i * 32 + l];
                ull wx = sp(w.x), wy = sp(w.y);
                fma2(a0P, vP, wx); fma2(a1P, vP, wy);
                fma2(a0Q, vQ, wx); fma2(a1Q, vQ, wy);
            }
            __syncwarp();
            float xa, xb;
            upk(a0P, xa, xb); sv2[l]      = make_float2(silu_n(xa*0.125f,cst), silu_n(xb*0.125f,cst));
            upk(a1P, xa, xb); sv2[32 + l] = make_float2(silu_n(xa*0.125f,cst), silu_n(xb*0.125f,cst));
            upk(a0Q, xa, xb); sv2[64 + l] = make_float2(silu_n(xa*0.125f,cst), silu_n(xb*0.125f,cst));
            upk(a1Q, xa, xb); sv2[96 + l] = make_float2(silu_n(xa*0.125f,cst), silu_n(xb*0.125f,cst));
            __syncwarp();
        }

        // ---- MLP stage 3: event weights (128 cols; lane holds l,l+32,l+64,l+96)
        ull bw0P = 0, bw1P = 0, bw2P = 0, bw3P = 0;
        ull bw0Q = 0, bw1Q = 0, bw2Q = 0, bw3Q = 0;
        #pragma unroll 8
        for (int i = 0; i < 64; i++) {
            ull vP = ldp(sv2 + i), vQ = ldp(sv2 + 64 + i);
            float4 w = sWm3[i * 32 + l];
            ull wx = sp(w.x), wy = sp(w.y), wz = sp(w.z), ww = sp(w.w);
            fma2(bw0P, vP, wx); fma2(bw1P, vP, wy); fma2(bw2P, vP, wz); fma2(bw3P, vP, ww);
            fma2(bw0Q, vQ, wx); fma2(bw1Q, vQ, wy); fma2(bw2Q, vQ, wz); fma2(bw3Q, vQ, ww);
        }
        // fold scales: weights/8 (and PW for the m1 branch)
        ull ws0P = mul2(bw0P, c8),   ws1P = mul2(bw1P, c8);
        ull ws2P = mul2(bw2P, cPW8), ws3P = mul2(bw3P, cPW8);
        ull ws0Q = mul2(bw0Q, c8),   ws1Q = mul2(bw1Q, c8);
        ull ws2Q = mul2(bw2Q, cPW8), ws3Q = mul2(bw3Q, cPW8);

        // ---- stage TP inputs (pair-interleaved)
        float4 yA = *(const float4*)(x2 + (size_t)e0 * 4);
        float4 yB = *(const float4*)(x2 + (size_t)e1 * 4);
        float4 yC = *(const float4*)(x2 + (size_t)e2 * 4);
        float4 yD = *(const float4*)(x2 + (size_t)e3 * 4);
        {
            const float* raA = x1a + (size_t)e0 * 128;  const float* rbA = x1b + (size_t)e0 * 128;
            const float* raB = x1a + (size_t)e1 * 128;  const float* rbB = x1b + (size_t)e1 * 128;
            const float* raC = x1a + (size_t)e2 * 128;  const float* rbC = x1b + (size_t)e2 * 128;
            const float* raD = x1a + (size_t)e3 * 128;  const float* rbD = x1b + (size_t)e3 * 128;

            sc2[l]      = make_float2(raA[l], raB[l]);
            sc2[32 + l] = make_float2(rbA[l], rbB[l]);
            sc2[64 + l] = make_float2(raC[l], raD[l]);
            sc2[96 + l] = make_float2(rbC[l], rbD[l]);
            #pragma unroll
            for (int k = 0; k < 3; k++) {
                int o = 32 + 3 * l + k;
                ss12[k * 128 + l]      = make_float2(raA[o], raB[o]);
                ss12[k * 128 + 32 + l] = make_float2(rbA[o], rbB[o]);
                ss12[k * 128 + 64 + l] = make_float2(raC[o], raD[o]);
                ss12[k * 128 + 96 + l] = make_float2(rbC[o], rbD[o]);
            }
        }
        __syncwarp();

        // ---- TP contractions (y hoisted out)
        ull t0P=0,qP=0,u0P=0,r0P=0,u1P=0,r1P=0,u2P=0,r2P=0;
        ull t0Q=0,qQ=0,u0Q=0,r0Q=0,u1Q=0,r1Q=0,u2Q=0,r2Q=0;
        #pragma unroll 8
        for (int i = 0; i < 64; i++) {
            ull cP  = ldp(sc2 + i),          cQ  = ldp(sc2 + 64 + i);
            ull s0P = ldp(ss12 + i),         s0Q = ldp(ss12 + 64 + i);
            ull s1P = ldp(ss12 + 128 + i),   s1Q = ldp(ss12 + 192 + i);
            ull s2P = ldp(ss12 + 256 + i),   s2Q = ldp(ss12 + 320 + i);
            float4 w = sW4[i * 32 + l];
            ull wx = sp(w.x), wy = sp(w.y), wz = sp(w.z), ww = sp(w.w);
            fma2(t0P, cP,  wx); fma2(qP,  cP,  wz);
            fma2(u0P, s0P, wy); fma2(r0P, s0P, ww);
            fma2(u1P, s1P, wy); fma2(r1P, s1P, ww);
            fma2(u2P, s2P, wy); fma2(r2P, s2P, ww);
            fma2(t0Q, cQ,  wx); fma2(qQ,  cQ,  wz);
            fma2(u0Q, s0Q, wy); fma2(r0Q, s0Q, ww);
            fma2(u1Q, s1Q, wy); fma2(r1Q, s1Q, ww);
            fma2(u2Q, s2Q, wy); fma2(r2Q, s2Q, ww);
        }
        __syncwarp();

        // ---- apply per-event scalars + weights, stage m-vectors (packed stores)
        {
            ull p0 = mul2(t0P, pk(PW * yA.x, PW * yB.x));
            ull p1 = mul2(u0P, pk(PWI * yA.y, PWI * yB.y));
            fma2(p1, u1P, pk(PWI * yA.z, PWI * yB.z));
            fma2(p1, u2P, pk(PWI * yA.w, PWI * yB.w));
            stp(sm02 + l,       mul2(p0, ws0P));
            stp(sm02 + 32 + l,  mul2(p1, ws1P));
            stp(smm2 + l,       mul2(qP, ws2P));
            stp(smr2 + l,       mul2(r0P, ws3P));
            stp(smr2 + 64 + l,  mul2(r1P, ws3P));
            stp(smr2 + 128 + l, mul2(r2P, ws3P));
        }
        {
            ull p0 = mul2(t0Q, pk(PW * yC.x, PW * yD.x));
            ull p1 = mul2(u0Q, pk(PWI * yC.y, PWI * yD.y));
            fma2(p1, u1Q, pk(PWI * yC.z, PWI * yD.z));
            fma2(p1, u2Q, pk(PWI * yC.w, PWI * yD.w));
            stp(sm02 + 64 + l,  mul2(p0, ws0Q));
            stp(sm02 + 96 + l,  mul2(p1, ws1Q));
            stp(smm2 + 32 + l,  mul2(qQ, ws2Q));
            stp(smr2 + 32 + l,  mul2(r0Q, ws3Q));
            stp(smr2 + 96 + l,  mul2(r1Q, ws3Q));
            stp(smr2 + 160 + l, mul2(r2Q, ws3Q));
        }
        __syncwarp();

        // ---- epilogue: fused (Wl @ Wf) projection
        ull o0P = 0, tlP = 0, k0P = 0, k1P = 0, k2P = 0;
        ull o0Q = 0, tlQ = 0, k0Q = 0, k1Q = 0, k2Q = 0;
        #pragma unroll 8
        for (int i = 0; i < 32; i++) {
            ull mP = ldp(sm02 + i),      mQ = ldp(sm02 + 64 + i);
            ull nP = ldp(smm2 + i),      nQ = ldp(smm2 + 32 + i);
            float2 g = sG[i * 32 + l];
            ull gx = sp(g.x), gy = sp(g.y);
            fma2(o0P, mP, gx); fma2(tlP, nP, gy);
            fma2(o0Q, mQ, gx); fma2(tlQ, nQ, gy);
        }
        #pragma unroll 8
        for (int i = 0; i < 32; i++) {
            ull mP  = ldp(sm02 + 32 + i), mQ  = ldp(sm02 + 96 + i);
            ull r0P_ = ldp(smr2 + i),      r0Q_ = ldp(smr2 + 32 + i);
            ull r1P_ = ldp(smr2 + 64 + i), r1Q_ = ldp(smr2 + 96 + i);
            ull r2P_ = ldp(smr2 + 128 + i),r2Q_ = ldp(smr2 + 160 + i);
            float2 g = sG[(32 + i) * 32 + l];
            ull gx = sp(g.x), gy = sp(g.y);
            fma2(o0P, mP,  gx);
            fma2(k0P, r0P_, gy); fma2(k1P, r1P_, gy); fma2(k2P, r2P_, gy);
            fma2(o0Q, mQ,  gx);
            fma2(k0Q, r0Q_, gy); fma2(k1Q, r1Q_, gy); fma2(k2Q, r2Q_, gy);
        }

        // ---- unpack + write out: [o0 (32) | o1 (32x3 row-major)]
        float oa, ob, ta, tb, a0, b0, a1, b1, a2, b2;
        {
            float* oA = out + (size_t)e0 * 128;
            float* oB = out + (size_t)e1 * 128;
            upk(o0P, oa, ob); upk(tlP, ta, tb);
            upk(k0P, a0, b0); upk(k1P, a1, b1); upk(k2P, a2, b2);
            oA[l]          = oa;
            oA[32 + 3 * l] = fmaf(yA.y, ta, yA.x * a0);
            oA[33 + 3 * l] = fmaf(yA.z, ta, yA.x * a1);
            oA[34 + 3 * l] = fmaf(yA.w, ta, yA.x * a2);
            oB[l]          = ob;
            oB[32 + 3 * l] = fmaf(yB.y, tb, yB.x * b0);
            oB[33 + 3 * l] = fmaf(yB.z, tb, yB.x * b1);
            oB[34 + 3 * l] = fmaf(yB.w, tb, yB.x * b2);
        }
        {
            float* oC = out + (size_t)e2 * 128;
            float* oD = out + (size_t)e3 * 128;
            upk(o0Q, oa, ob); upk(tlQ, ta, tb);
            upk(k0Q, a0, b0); upk(k1Q, a1, b1); upk(k2Q, a2, b2);
            oC[l]          = oa;
            oC[32 + 3 * l] = fmaf(yC.y, ta, yC.x * a0);
            oC[33 + 3 * l] = fmaf(yC.z, ta, yC.x * a1);
            oC[34 + 3 * l] = fmaf(yC.w, ta, yC.x * a2);
            oD[l]          = ob;
            oD[32 + 3 * l] = fmaf(yD.y, tb, yD.x * b0);
            oD[33 + 3 * l] = fmaf(yD.z, tb, yD.x * b1);
            oD[34 + 3 * l] = fmaf(yD.w, tb, yD.x * b2);
        }
    }
}

// ---------------- launch ----------------
extern "C" void kernel_launch(void* const* d_in, const int* in_sizes, int n_in,
                              void* d_out, int out_size) {
    const float* x1a     = (const float*)d_in[0];
    const float* x1b     = (const float*)d_in[1];
    const float* x2      = (const float*)d_in[2];
    const float* scalars = (const float*)d_in[3];
    const float* w0      = (const float*)d_in[4];
    const float* w1      = (const float*)d_in[5];
    const float* w2      = (const float*)d_in[6];
    const float* w3      = (const float*)d_in[7];
    const float* Wl0     = (const float*)d_in[8];
    const float* Wl1     = (const float*)d_in[9];
    const float* Wm1     = (const float*)d_in[10];
    const float* Wm2     = (const float*)d_in[11];
    const float* Wm3     = (const float*)d_in[12];
    const float* Wf0     = (const float*)d_in[13];
    const float* Wf1     = (const float*)d_in[14];
    const int E = in_sizes[0] / 128;

    k_integral<<<200, 256>>>();
    k_precompute<<<1, 256>>>(Wl0, Wf0, Wl1, Wf1);

    int sms = 148;
    cudaDeviceGetAttribute(&sms, cudaDevAttrMultiProcessorCount, 0);
    size_t smem = (size_t)(28672 + NW * WARP_F2 * 2) * sizeof(float);
    cudaFuncSetAttribute(k_main, cudaFuncAttributeMaxDynamicSharedMemorySize, (int)smem);
    k_main<<<sms, NTHREADS, smem>>>(x1a, x1b, x2, scalars, w0, w1, w2, w3,
                                    Wm1, Wm2, Wm3, (float*)d_out, E);
}